// round 10
// baseline (speedup 1.0000x reference)
#include <cuda_runtime.h>
#include <math.h>

// ---------------------------------------------------------------------------
// LinearDescent: linear attention with per-(b,h) 64x64 state reassociation.
// B=2, S=2048, H=1024, nh=16, hd=64, kg=8, din=128, P=2112, NPF=64.
// Round 10: mpart emits M^T; ctx inner loop fully d-paired (no pack movs),
// padded smem rows for conflict-free LDS.64. d-pair projections kept.
// ---------------------------------------------------------------------------

#define TOK_TOTAL 4096
#define S_LEN     2048
#define H_DIM     1024
#define NH        16
#define P_DIM     2112
#define NPF       64
#define DIN       128

typedef unsigned long long u64;

__device__ __forceinline__ u64 pack2b(float v) {
    u64 r; asm("mov.b64 %0, {%1,%1};" : "=l"(r) : "f"(v)); return r;
}
__device__ __forceinline__ u64 ffma2(u64 a, u64 b, u64 c) {
    u64 d; asm("fma.rn.f32x2 %0, %1, %2, %3;" : "=l"(d) : "l"(a), "l"(b), "l"(c)); return d;
}
__device__ __forceinline__ float2 unpk(u64 v) {
    float2 f; asm("mov.b64 {%0,%1}, %2;" : "=f"(f.x), "=f"(f.y) : "l"(v)); return f;
}

// scratch (device globals; allocation-free kernel_launch)
__device__ float g_k1[TOK_TOTAL * H_DIM];
__device__ float g_k [TOK_TOTAL * H_DIM];
__device__ float g_v [TOK_TOTAL * H_DIM];
__device__ float g_Mall[32 * 4096];   // per-(b,h) M^T[e][d] (atomic accum)
__device__ float g_M0  [32 * 4096];   // prefix-chunk contribution (M^T)
__device__ float g_WqT [16384];       // [g][h][d]
__device__ float g_WvT [16384];
__device__ float g_WcT [16384];
__device__ float g_WkhT[8192];        // [h8][g][dd]

__device__ __forceinline__ int pos_idx(int s) { return (s < NPF) ? (S_LEN + s) : s; }

// ---------------------------------------------------------------------------
// K0: weight transposes (tiny).
// ---------------------------------------------------------------------------
extern "C" __global__ void wprep_kernel(const float* __restrict__ Wq,
                                        const float* __restrict__ Wv,
                                        const float* __restrict__ Wc,
                                        const float* __restrict__ Wkh) {
    extern __shared__ float sw[];
    const int tid = threadIdx.x;
    const int bid = blockIdx.x;
    if (bid < 3) {
        const float* src = (bid == 0) ? Wq : (bid == 1) ? Wv : Wc;
        float*       dst = (bid == 0) ? g_WqT : (bid == 1) ? g_WvT : g_WcT;
        for (int i = tid; i < 4096; i += 256) ((float4*)sw)[i] = ((const float4*)src)[i];
        __syncthreads();
        for (int j = tid; j < 16384; j += 256) {
            int g = j >> 10, rem = j & 1023, h = rem >> 6, d = rem & 63;
            dst[j] = sw[d * 256 + h * 16 + g];
        }
    } else {
        for (int i = tid; i < 2048; i += 256) ((float4*)sw)[i] = ((const float4*)Wkh)[i];
        __syncthreads();
        for (int j = tid; j < 8192; j += 256) {
            int h8 = j >> 10, rem = j & 1023, g = rem >> 7, dd = rem & 127;
            g_WkhT[j] = sw[dd * 64 + g * 8 + h8];
        }
    }
}

// ---------------------------------------------------------------------------
// K1: k1[t, g*128+e] = sum_d hidden[t, g*128+d] * Wk_group[g, d, e]
//     + zeroing duty for g_Mall / g_M0.
// ---------------------------------------------------------------------------
extern "C" __global__ void k1_kernel(const float* __restrict__ hidden,
                                     const float* __restrict__ Wkg) {
    extern __shared__ float sm[];
    float* Ws = sm;            // 128*128
    float* Xs = sm + 16384;    // 64*16
    const int g   = blockIdx.y;
    const int t0  = blockIdx.x * 64;
    const int tid = threadIdx.x;

    if (blockIdx.x < 32) {
        float4 z = make_float4(0.f, 0.f, 0.f, 0.f);
        if (g == 0) {
            float4* p = (float4*)(g_Mall + (size_t)blockIdx.x * 4096);
#pragma unroll
            for (int i = 0; i < 4; i++) p[tid + i * 256] = z;
        } else if (g == 1) {
            float4* p = (float4*)(g_M0 + (size_t)blockIdx.x * 4096);
#pragma unroll
            for (int i = 0; i < 4; i++) p[tid + i * 256] = z;
        }
    }

    {
        const float4* wsrc = (const float4*)(Wkg + (size_t)g * 16384);
        float4* wdst = (float4*)Ws;
#pragma unroll
        for (int i = 0; i < 16; i++) wdst[tid + i * 256] = wsrc[tid + i * 256];
    }

    const int ct = tid & 15;
    const int rt = tid >> 4;
    u64 acc2[4][4];
#pragma unroll
    for (int j = 0; j < 4; j++)
#pragma unroll
        for (int c = 0; c < 4; c++) acc2[j][c] = 0ull;

    for (int kk = 0; kk < 128; kk += 16) {
        __syncthreads();
        {
            int row = tid >> 2, c4 = tid & 3;
            ((float4*)Xs)[tid] =
                *(const float4*)(hidden + (size_t)(t0 + row) * H_DIM + g * DIN + kk + c4 * 4);
        }
        __syncthreads();
#pragma unroll
        for (int i = 0; i < 16; i++) {
            const ulonglong2* wp = (const ulonglong2*)&Ws[(kk + i) * 128 + ct * 8];
            ulonglong2 wA = wp[0], wB = wp[1];
#pragma unroll
            for (int j = 0; j < 4; j++) {
                u64 xb = pack2b(Xs[(rt * 4 + j) * 16 + i]);
                acc2[j][0] = ffma2(xb, wA.x, acc2[j][0]);
                acc2[j][1] = ffma2(xb, wA.y, acc2[j][1]);
                acc2[j][2] = ffma2(xb, wB.x, acc2[j][2]);
                acc2[j][3] = ffma2(xb, wB.y, acc2[j][3]);
            }
        }
    }
#pragma unroll
    for (int j = 0; j < 4; j++) {
        float* o = g_k1 + (size_t)(t0 + rt * 4 + j) * H_DIM + g * DIN + ct * 8;
        ((ulonglong2*)o)[0] = make_ulonglong2(acc2[j][0], acc2[j][1]);
        ((ulonglong2*)o)[1] = make_ulonglong2(acc2[j][2], acc2[j][3]);
    }
}

// ---------------------------------------------------------------------------
// K2: k and v via d-pair ffma2 with transposed weights. 16 tok/block, 256 thr.
// ---------------------------------------------------------------------------
extern "C" __global__ void __launch_bounds__(256, 2)
kv_kernel(const float* __restrict__ hidden,
          const float* __restrict__ p_attn,
          const float* __restrict__ p_expand) {
    extern __shared__ float sm[];
    float* xs = sm;            // 16*1024
    float* ps = sm + 16384;    // 16*128
    const int tid  = threadIdx.x;
    const int tok0 = blockIdx.x * 16;

    {
        const float4* src = (const float4*)(hidden + (size_t)tok0 * H_DIM);
        float4* dst = (float4*)xs;
#pragma unroll
        for (int i = 0; i < 16; i++) dst[tid + i * 256] = src[tid + i * 256];
    }
#pragma unroll
    for (int i = 0; i < 8; i++) {
        int e = tid + i * 256;
        int t = e >> 7, c = e & 127;
        int s = (tok0 + t) & (S_LEN - 1);
        ps[e] = p_attn[(size_t)(64 + c) * P_DIM + pos_idx(s)];
    }
    __syncthreads();

    // ---- V ----
    {
        const int d0 = (tid & 31) * 2;
        const int g  = (tid >> 5) * 2;
        const u64* wv0 = (const u64*)(g_WvT + g * 1024 + d0);
        const u64* wv1 = (const u64*)(g_WvT + (g + 1) * 1024 + d0);
        const u64 pe0 = pack2b(p_expand[32 + g]);
        const u64 pe1 = pack2b(p_expand[33 + g]);
#pragma unroll
        for (int th = 0; th < 2; th++) {
            u64 acc[2][8];
#pragma unroll
            for (int t = 0; t < 8; t++) { acc[0][t] = 0ull; acc[1][t] = 0ull; }
#pragma unroll
            for (int h = 0; h < NH; h++) {
                u64 w0 = wv0[h * 32], w1 = wv1[h * 32];
#pragma unroll
                for (int t = 0; t < 8; t++) {
                    u64 x = *(const u64*)&xs[(th * 8 + t) * 1024 + h * 64 + d0];
                    acc[0][t] = ffma2(x, w0, acc[0][t]);
                    acc[1][t] = ffma2(x, w1, acc[1][t]);
                }
            }
#pragma unroll
            for (int t = 0; t < 8; t++) {
                int tt = th * 8 + t;
                u64 pv = *(const u64*)&ps[tt * 128 + 64 + d0];
                float* vb = g_v + (size_t)(tok0 + tt) * H_DIM;
                *(u64*)&vb[g * 64 + d0]       = ffma2(pe0, pv, acc[0][t]);
                *(u64*)&vb[(g + 1) * 64 + d0] = ffma2(pe1, pv, acc[1][t]);
            }
        }
    }
    // ---- K ----
    __syncthreads();
    {
        const float4* src = (const float4*)(g_k1 + (size_t)tok0 * H_DIM);
        float4* dst = (float4*)xs;
#pragma unroll
        for (int i = 0; i < 16; i++) dst[tid + i * 256] = src[tid + i * 256];
    }
    __syncthreads();
    {
        const int dd0 = (tid & 63) * 2;
        const int h8  = (tid >> 6) * 2;
        const u64* wk0 = (const u64*)(g_WkhT + h8 * 1024 + dd0);
        const u64* wk1 = (const u64*)(g_WkhT + (h8 + 1) * 1024 + dd0);
        const int jj0 = h8 * 128 + dd0;
        const int jj1 = (h8 + 1) * 128 + dd0;
        const u64 pe0 = pack2b(p_expand[16 + (jj0 >> 6)]);
        const u64 pe1 = pack2b(p_expand[16 + (jj1 >> 6)]);
        const int d64 = dd0 & 63;
#pragma unroll
        for (int th = 0; th < 2; th++) {
            u64 acc[2][8];
#pragma unroll
            for (int t = 0; t < 8; t++) { acc[0][t] = 0ull; acc[1][t] = 0ull; }
#pragma unroll
            for (int g = 0; g < 8; g++) {
                u64 w0 = wk0[g * 64], w1 = wk1[g * 64];
#pragma unroll
                for (int t = 0; t < 8; t++) {
                    u64 x = *(const u64*)&xs[(th * 8 + t) * 1024 + g * 128 + dd0];
                    acc[0][t] = ffma2(x, w0, acc[0][t]);
                    acc[1][t] = ffma2(x, w1, acc[1][t]);
                }
            }
#pragma unroll
            for (int t = 0; t < 8; t++) {
                int tt = th * 8 + t;
                u64 pk = *(const u64*)&ps[tt * 128 + d64];
                float* kb = g_k + (size_t)(tok0 + tt) * H_DIM;
                *(u64*)&kb[jj0] = ffma2(pe0, pk, acc[0][t]);
                *(u64*)&kb[jj1] = ffma2(pe1, pk, acc[1][t]);
            }
        }
    }
}

// ---------------------------------------------------------------------------
// K3: M^T partial per 64-token chunk -> RED.ADD into g_Mall (+g_M0 for c=0).
// MT[e][d] = sum_t v[t,e] * k[t,d]  (v on broadcast side, k on pair side).
// ---------------------------------------------------------------------------
extern "C" __global__ void mpart_kernel() {
    __shared__ float bs[64 * 64];   // broadcast side = v
    __shared__ float qs[64 * 64];   // pair side = k
    const int c = blockIdx.x, h = blockIdx.y, b = blockIdx.z;
    const int tid = threadIdx.x;
    const size_t tokbase = (size_t)(b * S_LEN + c * 64);
    const float* bp = g_v + tokbase * H_DIM + h * 64;   // v -> broadcast
    const float* pp = g_k + tokbase * H_DIM + h * 64;   // k -> pair
    for (int i = tid; i < 64 * 16; i += 128) {
        int row = i >> 4, c4 = i & 15;
        ((float4*)bs)[i] = *(const float4*)(bp + (size_t)row * H_DIM + c4 * 4);
        ((float4*)qs)[i] = *(const float4*)(pp + (size_t)row * H_DIM + c4 * 4);
    }
    __syncthreads();
    const int et = tid & 15;   // d = et*4..+3 (pair side)
    const int dt = tid >> 4;   // e = dt*8..+7 (broadcast side)
    u64 acc2[8][2];
#pragma unroll
    for (int i = 0; i < 8; i++) { acc2[i][0] = 0ull; acc2[i][1] = 0ull; }
#pragma unroll 2
    for (int t = 0; t < 64; t++) {
        ulonglong2 v2 = *(ulonglong2*)&qs[t * 64 + et * 4];
        float4 ka = *(float4*)&bs[t * 64 + dt * 8];
        float4 kb = *(float4*)&bs[t * 64 + dt * 8 + 4];
        float kv[8] = {ka.x, ka.y, ka.z, ka.w, kb.x, kb.y, kb.z, kb.w};
#pragma unroll
        for (int i = 0; i < 8; i++) {
            u64 kb2 = pack2b(kv[i]);
            acc2[i][0] = ffma2(kb2, v2.x, acc2[i][0]);
            acc2[i][1] = ffma2(kb2, v2.y, acc2[i][1]);
        }
    }
    // acc2[i] = MT[e = dt*8+i][d = et*4..+3]
    float* outp = g_Mall + (size_t)(b * 16 + h) * 4096;
    float* out0 = g_M0   + (size_t)(b * 16 + h) * 4096;
#pragma unroll
    for (int i = 0; i < 8; i++) {
        float2 a0 = unpk(acc2[i][0]), a1 = unpk(acc2[i][1]);
        int off = (dt * 8 + i) * 64 + et * 4;
        atomicAdd(&outp[off],     a0.x);
        atomicAdd(&outp[off + 1], a0.y);
        atomicAdd(&outp[off + 2], a1.x);
        atomicAdd(&outp[off + 3], a1.y);
        if (c == 0)
            *(ulonglong2*)&out0[off] = make_ulonglong2(acc2[i][0], acc2[i][1]);
    }
}

// ---------------------------------------------------------------------------
// K4: q (d-pair -> qT2[h][t][d], 66-padded rows), ctx = q @ M via MT rows
// (d-paired, no packs), Wc (d-pair), gates, blend.
// 16 tok/block, 512 thr, ~200KB smem, 1 CTA/SM.
// smem floats:
//   Mbuf [0, 16896)       hidden(16384) -> MT 4-head stage (4x4224) -> outs
//   qT2  [16896, 33792)   q: head*1056 + t*66 + d
//   C    [33792, 50176)   ctx natural [t][h*64+e]
//   psq  [50176, 51200), gs [51200, 51232)
// ---------------------------------------------------------------------------
extern "C" __global__ void __launch_bounds__(512, 1)
ctx_out_kernel(const float* __restrict__ hidden,
               const float* __restrict__ p_attn,
               const float* __restrict__ p_expand,
               const float* __restrict__ Wg,
               const float* __restrict__ Ug,
               const float* __restrict__ Vg,
               const float* __restrict__ bg,
               float* __restrict__ out) {
    extern __shared__ float sm[];
    float* Mbuf = sm;
    float* qT2  = sm + 16896;
    float* C    = sm + 33792;
    float* psq  = sm + 50176;
    float* gs   = sm + 51200;
    const int tid  = threadIdx.x;
    const int tok0 = blockIdx.x * 16;
    const int b    = tok0 / S_LEN;
    const int s0   = tok0 & (S_LEN - 1);
    const bool prefix = (s0 < NPF);

    {   // stage hidden into Mbuf (4096 float4)
        const float4* src = (const float4*)(hidden + (size_t)tok0 * H_DIM);
        float4* dst = (float4*)Mbuf;
#pragma unroll
        for (int i = 0; i < 8; i++) dst[tid + i * 512] = src[tid + i * 512];
    }
#pragma unroll
    for (int i = 0; i < 2; i++) {   // psq: 1024 entries
        int e = tid + i * 512;
        int t = e >> 6, d = e & 63;
        int s = (tok0 + t) & (S_LEN - 1);
        psq[e] = p_attn[(size_t)d * P_DIM + pos_idx(s)];
    }
    __syncthreads();

    // ---- Q -> qT2 : thread = (d-pair, head) ----
    {
        const int d0 = (tid & 31) * 2;
        const int g  = tid >> 5;           // 0..15
        const u64* wq = (const u64*)(g_WqT + g * 1024 + d0);
        u64 acc[16];
#pragma unroll
        for (int t = 0; t < 16; t++) acc[t] = 0ull;
#pragma unroll
        for (int h = 0; h < NH; h++) {
            u64 w = wq[h * 32];
#pragma unroll
            for (int t = 0; t < 16; t++)
                acc[t] = ffma2(*(const u64*)&Mbuf[t * 1024 + h * 64 + d0], w, acc[t]);
        }
        const u64 pe2 = pack2b(p_expand[g]);
        float* row = qT2 + g * 1056 + d0;
#pragma unroll
        for (int t = 0; t < 16; t++) {
            u64 pq = *(const u64*)&psq[t * 64 + d0];
            *(u64*)&row[t * 66] = ffma2(pe2, pq, acc[t]);
        }
    }

    // ---- ctx = q @ M : 4 stages x 4 heads, d-paired over MT rows ----
    const int wid  = tid >> 5;
    const int lane = tid & 31;
    const int hh   = wid >> 2;          // head within stage
    const int qe   = wid & 3;           // e quarter (16 e)
    const int tg   = lane >> 3;         // tokens tg*4..+3
    const int eg   = lane & 7;          // e pair: qe*16 + eg*2, +1
    const float* Ma = g_Mall + (size_t)(b * 16) * 4096;
    const float* M0 = g_M0   + (size_t)(b * 16) * 4096;

    for (int stg = 0; stg < 4; stg++) {
        __syncthreads();   // prior Mbuf fully consumed (stage0: Q phase done)
        {   // stage 4 heads of MT into Mbuf with 66-padded rows
            const u64* msrc = (const u64*)(Ma + (size_t)stg * 16384);
            const u64* zsrc = (const u64*)(M0 + (size_t)stg * 16384);
#pragma unroll
            for (int i = 0; i < 16; i++) {
                int j = tid + i * 512;                 // u64 index, 8192 total
                int h2 = j >> 11, e = (j >> 5) & 63, dp = j & 31;
                float* dst = Mbuf + h2 * 4224 + e * 66 + dp * 2;
                if (prefix) {
                    float2 A = unpk(msrc[j]), Z = unpk(zsrc[j]);
                    dst[0] = A.x - Z.x; dst[1] = A.y - Z.y;
                } else {
                    *(u64*)dst = msrc[j];
                }
            }
        }
        __syncthreads();

        const int head = stg * 4 + hh;
        const float* qrow = qT2 + head * 1056 + tg * 4 * 66;
        const float* mrow = Mbuf + hh * 4224 + (qe * 16 + eg * 2) * 66;
        u64 acc[4][2];
#pragma unroll
        for (int i = 0; i < 4; i++) { acc[i][0] = 0ull; acc[i][1] = 0ull; }
#pragma unroll 8
        for (int dl = 0; dl < 32; dl++) {
            u64 m0 = *(const u64*)(mrow + dl * 2);
            u64 m1 = *(const u64*)(mrow + 66 + dl * 2);
#pragma unroll
            for (int i = 0; i < 4; i++) {
                u64 q2 = *(const u64*)(qrow + i * 66 + dl * 2);
                acc[i][0] = ffma2(q2, m0, acc[i][0]);
                acc[i][1] = ffma2(q2, m1, acc[i][1]);
            }
        }
#pragma unroll
        for (int i = 0; i < 4; i++) {
            float2 a = unpk(acc[i][0]);
            float2 c2 = unpk(acc[i][1]);
            float2 r = make_float2(a.x + a.y, c2.x + c2.y);
            *(float2*)&C[(tg * 4 + i) * 1024 + head * 64 + qe * 16 + eg * 2] = r;
        }
    }
    __syncthreads();   // ctx complete in C; Mbuf free

    // ---- out = Wc head-mix (d-pair): read C, write outs into Mbuf ----
    {
        const int d0 = (tid & 31) * 2;
        const int g  = tid >> 5;
        const u64* wc = (const u64*)(g_WcT + g * 1024 + d0);
        u64 acc[16];
#pragma unroll
        for (int t = 0; t < 16; t++) acc[t] = 0ull;
#pragma unroll
        for (int h = 0; h < NH; h++) {
            u64 w = wc[h * 32];
#pragma unroll
            for (int t = 0; t < 16; t++)
                acc[t] = ffma2(*(const u64*)&C[t * 1024 + h * 64 + d0], w, acc[t]);
        }
#pragma unroll
        for (int t = 0; t < 16; t++)
            *(u64*)&Mbuf[t * 1024 + g * 64 + d0] = acc[t];
    }
    __syncthreads();

    // ---- gates: one warp per token; hidden re-read from global (L2-hot) ----
    {
        const int t = tid >> 5, sub = tid & 31;
        const float* hrow = hidden + (size_t)(tok0 + t) * H_DIM;
        float a0 = 0.f, a1 = 0.f;
#pragma unroll 8
        for (int k = 0; k < 32; k++) {
            int j = sub + k * 32;
            float hv = hrow[j];
            float ov = Mbuf[t * 1024 + j];
            a0 += hv * Wg[j]        + ov * Ug[j];
            a1 += hv * Wg[1024 + j] + ov * Ug[1024 + j];
        }
#pragma unroll
        for (int off = 16; off >= 1; off >>= 1) {
            a0 += __shfl_xor_sync(0xffffffffu, a0, off);
            a1 += __shfl_xor_sync(0xffffffffu, a1, off);
        }
        if (sub == 0) {
            int s  = (tok0 + t) & (S_LEN - 1);
            int ip = pos_idx(s);
            float z0 = a0 + Vg[ip] + bg[0];
            float z1 = a1 + Vg[P_DIM + ip] + bg[1];
            gs[t * 2]     = 1.f / (1.f + expf(-z0));
            gs[t * 2 + 1] = 1.f / (1.f + expf(-z1));
        }
    }
    __syncthreads();

    // ---- final blend (hidden from global, outs from Mbuf) ----
    {
        const float4* hsrc = (const float4*)(hidden + (size_t)tok0 * H_DIM);
        float4* od = (float4*)out;
#pragma unroll
        for (int i = 0; i < 8; i++) {
            int idx = tid + i * 512;
            int t = idx >> 8;
            float g0 = gs[t * 2], g1 = gs[t * 2 + 1];
            float4 ov = ((float4*)Mbuf)[idx];
            float4 hv = hsrc[idx];
            od[(size_t)tok0 * 256 + idx] =
                make_float4(g0 * ov.x + g1 * hv.x, g0 * ov.y + g1 * hv.y,
                            g0 * ov.z + g1 * hv.z, g0 * ov.w + g1 * hv.w);
        }
    }
}

// ---------------------------------------------------------------------------
extern "C" void kernel_launch(void* const* d_in, const int* in_sizes, int n_in,
                              void* d_out, int out_size) {
    const float* hidden   = (const float*)d_in[0];
    const float* Wq       = (const float*)d_in[3];
    const float* Wkg      = (const float*)d_in[4];
    const float* Wkh      = (const float*)d_in[5];
    const float* Wv       = (const float*)d_in[6];
    const float* p_attn   = (const float*)d_in[7];
    const float* p_expand = (const float*)d_in[8];
    const float* Wc       = (const float*)d_in[9];
    const float* Wg       = (const float*)d_in[10];
    const float* Ug       = (const float*)d_in[11];
    const float* Vg       = (const float*)d_in[12];
    const float* bg       = (const float*)d_in[13];
    float* out = (float*)d_out;

    cudaFuncSetAttribute(wprep_kernel,   cudaFuncAttributeMaxDynamicSharedMemorySize, 65536);
    cudaFuncSetAttribute(k1_kernel,      cudaFuncAttributeMaxDynamicSharedMemorySize, 69632);
    cudaFuncSetAttribute(kv_kernel,      cudaFuncAttributeMaxDynamicSharedMemorySize, 73728);
    cudaFuncSetAttribute(ctx_out_kernel, cudaFuncAttributeMaxDynamicSharedMemorySize, 204928);

    wprep_kernel<<<4, 256, 65536>>>(Wq, Wv, Wc, Wkh);
    k1_kernel<<<dim3(64, 8), 256, 69632>>>(hidden, Wkg);
    kv_kernel<<<256, 256, 73728>>>(hidden, p_attn, p_expand);
    mpart_kernel<<<dim3(32, 16, 2), 128>>>();
    ctx_out_kernel<<<256, 512, 204928>>>(hidden, p_attn, p_expand,
                                         Wg, Ug, Vg, bg, out);
}

// round 11
// speedup vs baseline: 1.1345x; 1.1345x over previous
#include <cuda_runtime.h>
#include <math.h>

// ---------------------------------------------------------------------------
// LinearDescent: linear attention with per-(b,h) 64x64 state reassociation.
// B=2, S=2048, H=1024, nh=16, hd=64, kg=8, din=128, P=2112, NPF=64.
// Round 11: tensor cores. mpart and ctx q@M use mma.sync.m16n8k8.tf32 with
// pre-converted tf32 smem tiles (padded, bank-conflict-free). Projections,
// k1, kv stay scalar ffma2 (d-pair).
// ---------------------------------------------------------------------------

#define TOK_TOTAL 4096
#define S_LEN     2048
#define H_DIM     1024
#define NH        16
#define P_DIM     2112
#define NPF       64
#define DIN       128

typedef unsigned long long u64;
typedef unsigned int u32;

__device__ __forceinline__ u64 pack2b(float v) {
    u64 r; asm("mov.b64 %0, {%1,%1};" : "=l"(r) : "f"(v)); return r;
}
__device__ __forceinline__ u64 ffma2(u64 a, u64 b, u64 c) {
    u64 d; asm("fma.rn.f32x2 %0, %1, %2, %3;" : "=l"(d) : "l"(a), "l"(b), "l"(c)); return d;
}
__device__ __forceinline__ float2 unpk(u64 v) {
    float2 f; asm("mov.b64 {%0,%1}, %2;" : "=f"(f.x), "=f"(f.y) : "l"(v)); return f;
}
__device__ __forceinline__ u32 tf32c(float f) {
    u32 r; asm("cvt.rna.tf32.f32 %0, %1;" : "=r"(r) : "f"(f)); return r;
}
__device__ __forceinline__ void mma_tf32(float* c, u32 a0, u32 a1, u32 a2, u32 a3,
                                         u32 b0, u32 b1) {
    asm volatile("mma.sync.aligned.m16n8k8.row.col.f32.tf32.tf32.f32 "
                 "{%0,%1,%2,%3}, {%4,%5,%6,%7}, {%8,%9}, {%0,%1,%2,%3};"
                 : "+f"(c[0]), "+f"(c[1]), "+f"(c[2]), "+f"(c[3])
                 : "r"(a0), "r"(a1), "r"(a2), "r"(a3), "r"(b0), "r"(b1));
}

// scratch (device globals; allocation-free kernel_launch)
__device__ float g_k1[TOK_TOTAL * H_DIM];
__device__ float g_k [TOK_TOTAL * H_DIM];
__device__ float g_v [TOK_TOTAL * H_DIM];
__device__ float g_Mall[32 * 4096];   // per-(b,h) MT[e][d] (atomic accum)
__device__ float g_M0  [32 * 4096];   // prefix-chunk contribution (MT)
__device__ float g_WqT [16384];       // [g][h][d]
__device__ float g_WvT [16384];
__device__ float g_WcT [16384];
__device__ float g_WkhT[8192];        // [h8][g][dd]

__device__ __forceinline__ int pos_idx(int s) { return (s < NPF) ? (S_LEN + s) : s; }

// ---------------------------------------------------------------------------
// K0: weight transposes (tiny).
// ---------------------------------------------------------------------------
extern "C" __global__ void wprep_kernel(const float* __restrict__ Wq,
                                        const float* __restrict__ Wv,
                                        const float* __restrict__ Wc,
                                        const float* __restrict__ Wkh) {
    extern __shared__ float sw[];
    const int tid = threadIdx.x;
    const int bid = blockIdx.x;
    if (bid < 3) {
        const float* src = (bid == 0) ? Wq : (bid == 1) ? Wv : Wc;
        float*       dst = (bid == 0) ? g_WqT : (bid == 1) ? g_WvT : g_WcT;
        for (int i = tid; i < 4096; i += 256) ((float4*)sw)[i] = ((const float4*)src)[i];
        __syncthreads();
        for (int j = tid; j < 16384; j += 256) {
            int g = j >> 10, rem = j & 1023, h = rem >> 6, d = rem & 63;
            dst[j] = sw[d * 256 + h * 16 + g];
        }
    } else {
        for (int i = tid; i < 2048; i += 256) ((float4*)sw)[i] = ((const float4*)Wkh)[i];
        __syncthreads();
        for (int j = tid; j < 8192; j += 256) {
            int h8 = j >> 10, rem = j & 1023, g = rem >> 7, dd = rem & 127;
            g_WkhT[j] = sw[dd * 64 + g * 8 + h8];
        }
    }
}

// ---------------------------------------------------------------------------
// K1: k1[t, g*128+e] = sum_d hidden[t, g*128+d] * Wk_group[g, d, e]
//     + zeroing duty for g_Mall / g_M0.
// ---------------------------------------------------------------------------
extern "C" __global__ void k1_kernel(const float* __restrict__ hidden,
                                     const float* __restrict__ Wkg) {
    extern __shared__ float sm[];
    float* Ws = sm;            // 128*128
    float* Xs = sm + 16384;    // 64*16
    const int g   = blockIdx.y;
    const int t0  = blockIdx.x * 64;
    const int tid = threadIdx.x;

    if (blockIdx.x < 32) {
        float4 z = make_float4(0.f, 0.f, 0.f, 0.f);
        if (g == 0) {
            float4* p = (float4*)(g_Mall + (size_t)blockIdx.x * 4096);
#pragma unroll
            for (int i = 0; i < 4; i++) p[tid + i * 256] = z;
        } else if (g == 1) {
            float4* p = (float4*)(g_M0 + (size_t)blockIdx.x * 4096);
#pragma unroll
            for (int i = 0; i < 4; i++) p[tid + i * 256] = z;
        }
    }

    {
        const float4* wsrc = (const float4*)(Wkg + (size_t)g * 16384);
        float4* wdst = (float4*)Ws;
#pragma unroll
        for (int i = 0; i < 16; i++) wdst[tid + i * 256] = wsrc[tid + i * 256];
    }

    const int ct = tid & 15;
    const int rt = tid >> 4;
    u64 acc2[4][4];
#pragma unroll
    for (int j = 0; j < 4; j++)
#pragma unroll
        for (int c = 0; c < 4; c++) acc2[j][c] = 0ull;

    for (int kk = 0; kk < 128; kk += 16) {
        __syncthreads();
        {
            int row = tid >> 2, c4 = tid & 3;
            ((float4*)Xs)[tid] =
                *(const float4*)(hidden + (size_t)(t0 + row) * H_DIM + g * DIN + kk + c4 * 4);
        }
        __syncthreads();
#pragma unroll
        for (int i = 0; i < 16; i++) {
            const ulonglong2* wp = (const ulonglong2*)&Ws[(kk + i) * 128 + ct * 8];
            ulonglong2 wA = wp[0], wB = wp[1];
#pragma unroll
            for (int j = 0; j < 4; j++) {
                u64 xb = pack2b(Xs[(rt * 4 + j) * 16 + i]);
                acc2[j][0] = ffma2(xb, wA.x, acc2[j][0]);
                acc2[j][1] = ffma2(xb, wA.y, acc2[j][1]);
                acc2[j][2] = ffma2(xb, wB.x, acc2[j][2]);
                acc2[j][3] = ffma2(xb, wB.y, acc2[j][3]);
            }
        }
    }
#pragma unroll
    for (int j = 0; j < 4; j++) {
        float* o = g_k1 + (size_t)(t0 + rt * 4 + j) * H_DIM + g * DIN + ct * 8;
        ((ulonglong2*)o)[0] = make_ulonglong2(acc2[j][0], acc2[j][1]);
        ((ulonglong2*)o)[1] = make_ulonglong2(acc2[j][2], acc2[j][3]);
    }
}

// ---------------------------------------------------------------------------
// K2: k and v via d-pair ffma2 with transposed weights. 16 tok/block, 256 thr.
// ---------------------------------------------------------------------------
extern "C" __global__ void __launch_bounds__(256, 2)
kv_kernel(const float* __restrict__ hidden,
          const float* __restrict__ p_attn,
          const float* __restrict__ p_expand) {
    extern __shared__ float sm[];
    float* xs = sm;            // 16*1024
    float* ps = sm + 16384;    // 16*128
    const int tid  = threadIdx.x;
    const int tok0 = blockIdx.x * 16;

    {
        const float4* src = (const float4*)(hidden + (size_t)tok0 * H_DIM);
        float4* dst = (float4*)xs;
#pragma unroll
        for (int i = 0; i < 16; i++) dst[tid + i * 256] = src[tid + i * 256];
    }
#pragma unroll
    for (int i = 0; i < 8; i++) {
        int e = tid + i * 256;
        int t = e >> 7, c = e & 127;
        int s = (tok0 + t) & (S_LEN - 1);
        ps[e] = p_attn[(size_t)(64 + c) * P_DIM + pos_idx(s)];
    }
    __syncthreads();

    // ---- V ----
    {
        const int d0 = (tid & 31) * 2;
        const int g  = (tid >> 5) * 2;
        const u64* wv0 = (const u64*)(g_WvT + g * 1024 + d0);
        const u64* wv1 = (const u64*)(g_WvT + (g + 1) * 1024 + d0);
        const u64 pe0 = pack2b(p_expand[32 + g]);
        const u64 pe1 = pack2b(p_expand[33 + g]);
#pragma unroll
        for (int th = 0; th < 2; th++) {
            u64 acc[2][8];
#pragma unroll
            for (int t = 0; t < 8; t++) { acc[0][t] = 0ull; acc[1][t] = 0ull; }
#pragma unroll
            for (int h = 0; h < NH; h++) {
                u64 w0 = wv0[h * 32], w1 = wv1[h * 32];
#pragma unroll
                for (int t = 0; t < 8; t++) {
                    u64 x = *(const u64*)&xs[(th * 8 + t) * 1024 + h * 64 + d0];
                    acc[0][t] = ffma2(x, w0, acc[0][t]);
                    acc[1][t] = ffma2(x, w1, acc[1][t]);
                }
            }
#pragma unroll
            for (int t = 0; t < 8; t++) {
                int tt = th * 8 + t;
                u64 pv = *(const u64*)&ps[tt * 128 + 64 + d0];
                float* vb = g_v + (size_t)(tok0 + tt) * H_DIM;
                *(u64*)&vb[g * 64 + d0]       = ffma2(pe0, pv, acc[0][t]);
                *(u64*)&vb[(g + 1) * 64 + d0] = ffma2(pe1, pv, acc[1][t]);
            }
        }
    }
    // ---- K ----
    __syncthreads();
    {
        const float4* src = (const float4*)(g_k1 + (size_t)tok0 * H_DIM);
        float4* dst = (float4*)xs;
#pragma unroll
        for (int i = 0; i < 16; i++) dst[tid + i * 256] = src[tid + i * 256];
    }
    __syncthreads();
    {
        const int dd0 = (tid & 63) * 2;
        const int h8  = (tid >> 6) * 2;
        const u64* wk0 = (const u64*)(g_WkhT + h8 * 1024 + dd0);
        const u64* wk1 = (const u64*)(g_WkhT + (h8 + 1) * 1024 + dd0);
        const int jj0 = h8 * 128 + dd0;
        const int jj1 = (h8 + 1) * 128 + dd0;
        const u64 pe0 = pack2b(p_expand[16 + (jj0 >> 6)]);
        const u64 pe1 = pack2b(p_expand[16 + (jj1 >> 6)]);
        const int d64 = dd0 & 63;
#pragma unroll
        for (int th = 0; th < 2; th++) {
            u64 acc[2][8];
#pragma unroll
            for (int t = 0; t < 8; t++) { acc[0][t] = 0ull; acc[1][t] = 0ull; }
#pragma unroll
            for (int g = 0; g < 8; g++) {
                u64 w0 = wk0[g * 64], w1 = wk1[g * 64];
#pragma unroll
                for (int t = 0; t < 8; t++) {
                    u64 x = *(const u64*)&xs[(th * 8 + t) * 1024 + g * 128 + dd0];
                    acc[0][t] = ffma2(x, w0, acc[0][t]);
                    acc[1][t] = ffma2(x, w1, acc[1][t]);
                }
            }
#pragma unroll
            for (int t = 0; t < 8; t++) {
                int tt = th * 8 + t;
                u64 pk = *(const u64*)&ps[tt * 128 + d64];
                float* kb = g_k + (size_t)(tok0 + tt) * H_DIM;
                *(u64*)&kb[jj0] = ffma2(pe0, pk, acc[0][t]);
                *(u64*)&kb[jj1] = ffma2(pe1, pk, acc[1][t]);
            }
        }
    }
}

// ---------------------------------------------------------------------------
// K3: MT[e][d] += sum_t v[t,e]*k[t,d] per 64-token chunk via tf32 mma.
// grid (32,16,2), 128 thr (4 warps; warp = 16-e slice).
// A = v (row e, col t), B = k (row t, col d), tf32 tiles padded stride 72.
// ---------------------------------------------------------------------------
extern "C" __global__ void mpart_kernel() {
    __shared__ u32 vs[64 * 72];
    __shared__ u32 ks[64 * 72];
    const int c = blockIdx.x, h = blockIdx.y, b = blockIdx.z;
    const int tid = threadIdx.x;
    const size_t tokbase = (size_t)(b * S_LEN + c * 64);
    const float* vp = g_v + tokbase * H_DIM + h * 64;
    const float* kp = g_k + tokbase * H_DIM + h * 64;
#pragma unroll
    for (int it = 0; it < 8; it++) {
        int i = tid + it * 128;
        int row = i >> 4, c4 = (i & 15) * 4;
        float4 v4 = *(const float4*)(vp + (size_t)row * H_DIM + c4);
        float4 k4 = *(const float4*)(kp + (size_t)row * H_DIM + c4);
        u32* vd = vs + row * 72 + c4;
        u32* kd = ks + row * 72 + c4;
        vd[0] = tf32c(v4.x); vd[1] = tf32c(v4.y); vd[2] = tf32c(v4.z); vd[3] = tf32c(v4.w);
        kd[0] = tf32c(k4.x); kd[1] = tf32c(k4.y); kd[2] = tf32c(k4.z); kd[3] = tf32c(k4.w);
    }
    __syncthreads();

    const int wid = tid >> 5, lane = tid & 31;
    const int gID = lane >> 2, tID = lane & 3;
    const int e0 = wid * 16;
    float acc[8][4];
#pragma unroll
    for (int n = 0; n < 8; n++)
#pragma unroll
        for (int j = 0; j < 4; j++) acc[n][j] = 0.f;

#pragma unroll
    for (int ks8 = 0; ks8 < 8; ks8++) {
        const int t0 = ks8 * 8;
        u32 a0 = vs[(t0 + tID) * 72 + e0 + gID];
        u32 a1 = vs[(t0 + tID) * 72 + e0 + gID + 8];
        u32 a2 = vs[(t0 + tID + 4) * 72 + e0 + gID];
        u32 a3 = vs[(t0 + tID + 4) * 72 + e0 + gID + 8];
#pragma unroll
        for (int n = 0; n < 8; n++) {
            u32 b0 = ks[(t0 + tID) * 72 + n * 8 + gID];
            u32 b1 = ks[(t0 + tID + 4) * 72 + n * 8 + gID];
            mma_tf32(acc[n], a0, a1, a2, a3, b0, b1);
        }
    }

    float* outp = g_Mall + (size_t)(b * 16 + h) * 4096;
    float* out0 = g_M0   + (size_t)(b * 16 + h) * 4096;
    const int er0 = e0 + gID, er1 = e0 + gID + 8;
#pragma unroll
    for (int n = 0; n < 8; n++) {
        int d = n * 8 + tID * 2;
        atomicAdd(&outp[er0 * 64 + d],     acc[n][0]);
        atomicAdd(&outp[er0 * 64 + d + 1], acc[n][1]);
        atomicAdd(&outp[er1 * 64 + d],     acc[n][2]);
        atomicAdd(&outp[er1 * 64 + d + 1], acc[n][3]);
        if (c == 0) {
            *(float2*)&out0[er0 * 64 + d] = make_float2(acc[n][0], acc[n][1]);
            *(float2*)&out0[er1 * 64 + d] = make_float2(acc[n][2], acc[n][3]);
        }
    }
}

// ---------------------------------------------------------------------------
// K4: Q proj (d-pair, tf32 into qp), ctx = q @ M via tf32 mma (4 stages x
// 4 heads; 4 warps/head over e quarters), Wc (d-pair), gates, blend.
// 16 tok/block, 512 thr, 225.4KB smem, 1 CTA/SM.
// smem floats:
//   X    [0, 16384)       hidden -> C (ctx results, [t][h*64+e])
//   qp   [16384, 35840)   tf32 q: head*1216 + t*76 + d   (19456 floats)
//   Mbuf [35840, 55296)   tf32 MT stage: hh*4864 + e*76 + d (19456 floats)
//                         -> outs (flat [t][1024]) after last stage
//   psq  [55296, 56320), gs [56320, 56352)
// ---------------------------------------------------------------------------
extern "C" __global__ void __launch_bounds__(512, 1)
ctx_out_kernel(const float* __restrict__ hidden,
               const float* __restrict__ p_attn,
               const float* __restrict__ p_expand,
               const float* __restrict__ Wg,
               const float* __restrict__ Ug,
               const float* __restrict__ Vg,
               const float* __restrict__ bg,
               float* __restrict__ out) {
    extern __shared__ float sm[];
    float* X    = sm;
    u32*   qpu  = (u32*)(sm + 16384);
    u32*   Mu   = (u32*)(sm + 35840);
    float* Mout = sm + 35840;
    float* psq  = sm + 55296;
    float* gs   = sm + 56320;
    const int tid  = threadIdx.x;
    const int tok0 = blockIdx.x * 16;
    const int b    = tok0 / S_LEN;
    const int s0   = tok0 & (S_LEN - 1);
    const bool prefix = (s0 < NPF);

    {   // stage hidden into X (4096 float4)
        const float4* src = (const float4*)(hidden + (size_t)tok0 * H_DIM);
        float4* dst = (float4*)X;
#pragma unroll
        for (int i = 0; i < 8; i++) dst[tid + i * 512] = src[tid + i * 512];
    }
#pragma unroll
    for (int i = 0; i < 2; i++) {   // psq: 1024 entries
        int e = tid + i * 512;
        int t = e >> 6, d = e & 63;
        int s = (tok0 + t) & (S_LEN - 1);
        psq[e] = p_attn[(size_t)d * P_DIM + pos_idx(s)];
    }
    __syncthreads();

    // ---- Q -> qp (tf32, padded stride 76) : thread = (d-pair, head) ----
    {
        const int d0 = (tid & 31) * 2;
        const int g  = tid >> 5;
        const u64* wq = (const u64*)(g_WqT + g * 1024 + d0);
        u64 acc[16];
#pragma unroll
        for (int t = 0; t < 16; t++) acc[t] = 0ull;
#pragma unroll
        for (int h = 0; h < NH; h++) {
            u64 w = wq[h * 32];
#pragma unroll
            for (int t = 0; t < 16; t++)
                acc[t] = ffma2(*(const u64*)&X[t * 1024 + h * 64 + d0], w, acc[t]);
        }
        const u64 pe2 = pack2b(p_expand[g]);
        u32* row = qpu + g * 1216 + d0;
#pragma unroll
        for (int t = 0; t < 16; t++) {
            u64 pq = *(const u64*)&psq[t * 64 + d0];
            float2 a = unpk(ffma2(pe2, pq, acc[t]));
            row[t * 76]     = tf32c(a.x);
            row[t * 76 + 1] = tf32c(a.y);
        }
    }

    // ---- ctx = q @ M via mma : 4 stages x 4 heads ----
    const int wid  = tid >> 5;
    const int lane = tid & 31;
    const int gID  = lane >> 2, tID = lane & 3;
    const int hh   = wid >> 2;          // head within stage
    const int nq   = wid & 3;           // e quarter (2 n-tiles)
    const float* Ma = g_Mall + (size_t)(b * 16) * 4096;
    const float* M0 = g_M0   + (size_t)(b * 16) * 4096;

    for (int stg = 0; stg < 4; stg++) {
        __syncthreads();   // stg0: Q done (X reads, qp writes); else Mbuf/C consumed
        {   // stage 4 heads of MT into Mu (tf32, stride 76)
            const u64* msrc = (const u64*)(Ma + (size_t)stg * 16384);
            const u64* zsrc = (const u64*)(M0 + (size_t)stg * 16384);
#pragma unroll
            for (int i = 0; i < 16; i++) {
                int j = tid + i * 512;                 // 8192 u64
                int h2 = j >> 11, e = (j >> 5) & 63, dp = (j & 31) * 2;
                float2 A = unpk(msrc[j]);
                if (prefix) {
                    float2 Z = unpk(zsrc[j]);
                    A.x -= Z.x; A.y -= Z.y;
                }
                u32* dst = Mu + h2 * 4864 + e * 76 + dp;
                dst[0] = tf32c(A.x);
                dst[1] = tf32c(A.y);
            }
        }
        __syncthreads();

        const int head = stg * 4 + hh;
        const u32* qb = qpu + head * 1216;
        const u32* mb = Mu + hh * 4864;
        float acc[2][4];
#pragma unroll
        for (int j = 0; j < 2; j++)
#pragma unroll
            for (int i = 0; i < 4; i++) acc[j][i] = 0.f;
#pragma unroll
        for (int ks8 = 0; ks8 < 8; ks8++) {
            const int k0 = ks8 * 8;
            u32 a0 = qb[gID * 76 + k0 + tID];
            u32 a1 = qb[(gID + 8) * 76 + k0 + tID];
            u32 a2 = qb[gID * 76 + k0 + tID + 4];
            u32 a3 = qb[(gID + 8) * 76 + k0 + tID + 4];
#pragma unroll
            for (int j = 0; j < 2; j++) {
                int nt = nq * 2 + j;
                u32 b0 = mb[(nt * 8 + gID) * 76 + k0 + tID];
                u32 b1 = mb[(nt * 8 + gID) * 76 + k0 + tID + 4];
                mma_tf32(acc[j], a0, a1, a2, a3, b0, b1);
            }
        }
#pragma unroll
        for (int j = 0; j < 2; j++) {
            int col = head * 64 + (nq * 2 + j) * 8 + 2 * tID;
            *(float2*)&X[gID * 1024 + col]       = make_float2(acc[j][0], acc[j][1]);
            *(float2*)&X[(gID + 8) * 1024 + col] = make_float2(acc[j][2], acc[j][3]);
        }
    }
    __syncthreads();   // ctx complete in X; Mu free

    // ---- out = Wc head-mix (d-pair): read X(C), write outs into Mout ----
    {
        const int d0 = (tid & 31) * 2;
        const int g  = tid >> 5;
        const u64* wc = (const u64*)(g_WcT + g * 1024 + d0);
        u64 acc[16];
#pragma unroll
        for (int t = 0; t < 16; t++) acc[t] = 0ull;
#pragma unroll
        for (int h = 0; h < NH; h++) {
            u64 w = wc[h * 32];
#pragma unroll
            for (int t = 0; t < 16; t++)
                acc[t] = ffma2(*(const u64*)&X[t * 1024 + h * 64 + d0], w, acc[t]);
        }
        __syncthreads();   // all X reads done before Mout overwrite? (Mout != X; safe)
#pragma unroll
        for (int t = 0; t < 16; t++)
            *(u64*)&Mout[t * 1024 + g * 64 + d0] = acc[t];
    }
    __syncthreads();

    // ---- gates: one warp per token; hidden re-read from global (L2-hot) ----
    {
        const int t = tid >> 5, sub = tid & 31;
        const float* hrow = hidden + (size_t)(tok0 + t) * H_DIM;
        float a0 = 0.f, a1 = 0.f;
#pragma unroll 8
        for (int k = 0; k < 32; k++) {
            int j = sub + k * 32;
            float hv = hrow[j];
            float ov = Mout[t * 1024 + j];
            a0 += hv * Wg[j]        + ov * Ug[j];
            a1 += hv * Wg[1024 + j] + ov * Ug[1024 + j];
        }
#pragma unroll
        for (int off = 16; off >= 1; off >>= 1) {
            a0 += __shfl_xor_sync(0xffffffffu, a0, off);
            a1 += __shfl_xor_sync(0xffffffffu, a1, off);
        }
        if (sub == 0) {
            int s  = (tok0 + t) & (S_LEN - 1);
            int ip = pos_idx(s);
            float z0 = a0 + Vg[ip] + bg[0];
            float z1 = a1 + Vg[P_DIM + ip] + bg[1];
            gs[t * 2]     = 1.f / (1.f + expf(-z0));
            gs[t * 2 + 1] = 1.f / (1.f + expf(-z1));
        }
    }
    __syncthreads();

    // ---- final blend (hidden from global, outs from Mout) ----
    {
        const float4* hsrc = (const float4*)(hidden + (size_t)tok0 * H_DIM);
        float4* od = (float4*)out;
#pragma unroll
        for (int i = 0; i < 8; i++) {
            int idx = tid + i * 512;
            int t = idx >> 8;
            float g0 = gs[t * 2], g1 = gs[t * 2 + 1];
            float4 ov = ((float4*)Mout)[idx];
            float4 hv = hsrc[idx];
            od[(size_t)tok0 * 256 + idx] =
                make_float4(g0 * ov.x + g1 * hv.x, g0 * ov.y + g1 * hv.y,
                            g0 * ov.z + g1 * hv.z, g0 * ov.w + g1 * hv.w);
        }
    }
}

// ---------------------------------------------------------------------------
extern "C" void kernel_launch(void* const* d_in, const int* in_sizes, int n_in,
                              void* d_out, int out_size) {
    const float* hidden   = (const float*)d_in[0];
    const float* Wq       = (const float*)d_in[3];
    const float* Wkg      = (const float*)d_in[4];
    const float* Wkh      = (const float*)d_in[5];
    const float* Wv       = (const float*)d_in[6];
    const float* p_attn   = (const float*)d_in[7];
    const float* p_expand = (const float*)d_in[8];
    const float* Wc       = (const float*)d_in[9];
    const float* Wg       = (const float*)d_in[10];
    const float* Ug       = (const float*)d_in[11];
    const float* Vg       = (const float*)d_in[12];
    const float* bg       = (const float*)d_in[13];
    float* out = (float*)d_out;

    cudaFuncSetAttribute(wprep_kernel,   cudaFuncAttributeMaxDynamicSharedMemorySize, 65536);
    cudaFuncSetAttribute(k1_kernel,      cudaFuncAttributeMaxDynamicSharedMemorySize, 69632);
    cudaFuncSetAttribute(kv_kernel,      cudaFuncAttributeMaxDynamicSharedMemorySize, 73728);
    cudaFuncSetAttribute(ctx_out_kernel, cudaFuncAttributeMaxDynamicSharedMemorySize, 225408);

    wprep_kernel<<<4, 256, 65536>>>(Wq, Wv, Wc, Wkh);
    k1_kernel<<<dim3(64, 8), 256, 69632>>>(hidden, Wkg);
    kv_kernel<<<256, 256, 73728>>>(hidden, p_attn, p_expand);
    mpart_kernel<<<dim3(32, 16, 2), 128>>>();
    ctx_out_kernel<<<256, 512, 225408>>>(hidden, p_attn, p_expand,
                                         Wg, Ug, Vg, bg, out);
}

// round 12
// speedup vs baseline: 1.4544x; 1.2820x over previous
#include <cuda_runtime.h>
#include <math.h>

// ---------------------------------------------------------------------------
// LinearDescent: linear attention with per-(b,h) 64x64 state reassociation.
// B=2, S=2048, H=1024, nh=16, hd=64, kg=8, din=128, P=2112, NPF=64.
// Round 12: k1 moved to tf32 mma (validated fragment conventions from R11);
// all tf32 conversions dropped (raw fp32 bits as tf32 operands).
// ---------------------------------------------------------------------------

#define TOK_TOTAL 4096
#define S_LEN     2048
#define H_DIM     1024
#define NH        16
#define P_DIM     2112
#define NPF       64
#define DIN       128

typedef unsigned long long u64;
typedef unsigned int u32;

__device__ __forceinline__ u64 pack2b(float v) {
    u64 r; asm("mov.b64 %0, {%1,%1};" : "=l"(r) : "f"(v)); return r;
}
__device__ __forceinline__ u64 ffma2(u64 a, u64 b, u64 c) {
    u64 d; asm("fma.rn.f32x2 %0, %1, %2, %3;" : "=l"(d) : "l"(a), "l"(b), "l"(c)); return d;
}
__device__ __forceinline__ float2 unpk(u64 v) {
    float2 f; asm("mov.b64 {%0,%1}, %2;" : "=f"(f.x), "=f"(f.y) : "l"(v)); return f;
}
__device__ __forceinline__ void mma_tf32(float* c, u32 a0, u32 a1, u32 a2, u32 a3,
                                         u32 b0, u32 b1) {
    asm volatile("mma.sync.aligned.m16n8k8.row.col.f32.tf32.tf32.f32 "
                 "{%0,%1,%2,%3}, {%4,%5,%6,%7}, {%8,%9}, {%0,%1,%2,%3};"
                 : "+f"(c[0]), "+f"(c[1]), "+f"(c[2]), "+f"(c[3])
                 : "r"(a0), "r"(a1), "r"(a2), "r"(a3), "r"(b0), "r"(b1));
}

// scratch (device globals; allocation-free kernel_launch)
__device__ float g_k1[TOK_TOTAL * H_DIM];
__device__ float g_k [TOK_TOTAL * H_DIM];
__device__ float g_v [TOK_TOTAL * H_DIM];
__device__ float g_Mall[32 * 4096];   // per-(b,h) MT[e][d] (atomic accum)
__device__ float g_M0  [32 * 4096];   // prefix-chunk contribution (MT)
__device__ float g_WqT [16384];       // [g][h][d]
__device__ float g_WvT [16384];
__device__ float g_WcT [16384];
__device__ float g_WkhT[8192];        // [h8][g][dd]

__device__ __forceinline__ int pos_idx(int s) { return (s < NPF) ? (S_LEN + s) : s; }

// ---------------------------------------------------------------------------
// K0: weight transposes (tiny).
// ---------------------------------------------------------------------------
extern "C" __global__ void wprep_kernel(const float* __restrict__ Wq,
                                        const float* __restrict__ Wv,
                                        const float* __restrict__ Wc,
                                        const float* __restrict__ Wkh) {
    extern __shared__ float sw[];
    const int tid = threadIdx.x;
    const int bid = blockIdx.x;
    if (bid < 3) {
        const float* src = (bid == 0) ? Wq : (bid == 1) ? Wv : Wc;
        float*       dst = (bid == 0) ? g_WqT : (bid == 1) ? g_WvT : g_WcT;
        for (int i = tid; i < 4096; i += 256) ((float4*)sw)[i] = ((const float4*)src)[i];
        __syncthreads();
        for (int j = tid; j < 16384; j += 256) {
            int g = j >> 10, rem = j & 1023, h = rem >> 6, d = rem & 63;
            dst[j] = sw[d * 256 + h * 16 + g];
        }
    } else {
        for (int i = tid; i < 2048; i += 256) ((float4*)sw)[i] = ((const float4*)Wkh)[i];
        __syncthreads();
        for (int j = tid; j < 8192; j += 256) {
            int h8 = j >> 10, rem = j & 1023, g = rem >> 7, dd = rem & 127;
            g_WkhT[j] = sw[dd * 64 + g * 8 + h8];
        }
    }
}

// ---------------------------------------------------------------------------
// K1: k1[t, g*128+e] = sum_d hidden[t, g*128+d] * Wk_group[g, d, e]
// via tf32 mma. 64 tok x 128 out per block, grid (64, 8), 256 thr, 2 CTA/SM.
// smem: Xs 64x132 (A clean banks), Ws 128x136 (B clean banks). 103424 B.
// Also zeroes g_Mall / g_M0 (precedes mpart in stream order).
// ---------------------------------------------------------------------------
extern "C" __global__ void __launch_bounds__(256, 2)
k1_kernel(const float* __restrict__ hidden, const float* __restrict__ Wkg) {
    extern __shared__ float sm[];
    float* Xs = sm;              // 64*132 = 8448
    float* Ws = sm + 8448;       // 128*136 = 17408
    const int g   = blockIdx.y;
    const int t0  = blockIdx.x * 64;
    const int tid = threadIdx.x;

    if (blockIdx.x < 32) {
        float4 z = make_float4(0.f, 0.f, 0.f, 0.f);
        if (g == 0) {
            float4* p = (float4*)(g_Mall + (size_t)blockIdx.x * 4096);
#pragma unroll
            for (int i = 0; i < 4; i++) p[tid + i * 256] = z;
        } else if (g == 1) {
            float4* p = (float4*)(g_M0 + (size_t)blockIdx.x * 4096);
#pragma unroll
            for (int i = 0; i < 4; i++) p[tid + i * 256] = z;
        }
    }

#pragma unroll
    for (int i = 0; i < 8; i++) {        // Xs: 2048 float4
        int j = tid + i * 256;
        int row = j >> 5, c4 = (j & 31) * 4;
        *(float4*)&Xs[row * 132 + c4] =
            *(const float4*)(hidden + (size_t)(t0 + row) * H_DIM + g * DIN + c4);
    }
#pragma unroll
    for (int i = 0; i < 16; i++) {       // Ws: 4096 float4
        int j = tid + i * 256;
        int row = j >> 5, c4 = (j & 31) * 4;
        *(float4*)&Ws[row * 136 + c4] =
            *(const float4*)(Wkg + (size_t)g * 16384 + row * 128 + c4);
    }
    __syncthreads();

    const int lane = tid & 31, wid = tid >> 5;
    const int gID = lane >> 2, tID = lane & 3;
    const int mt = wid & 3;              // m-tile: rows mt*16
    const int nh = wid >> 2;             // n-half: cols nh*64
    float acc[8][4];
#pragma unroll
    for (int n = 0; n < 8; n++)
#pragma unroll
        for (int j = 0; j < 4; j++) acc[n][j] = 0.f;

    const float* Ar0 = Xs + (mt * 16 + gID) * 132;
    const float* Ar1 = Ar0 + 8 * 132;
    const float* Bbase = Ws + nh * 64 + gID;
#pragma unroll
    for (int k0 = 0; k0 < 128; k0 += 8) {
        u32 a0 = __float_as_uint(Ar0[k0 + tID]);
        u32 a1 = __float_as_uint(Ar1[k0 + tID]);
        u32 a2 = __float_as_uint(Ar0[k0 + tID + 4]);
        u32 a3 = __float_as_uint(Ar1[k0 + tID + 4]);
        const float* B0 = Bbase + (k0 + tID) * 136;
        const float* B1 = B0 + 4 * 136;
#pragma unroll
        for (int n = 0; n < 8; n++) {
            u32 b0 = __float_as_uint(B0[n * 8]);
            u32 b1 = __float_as_uint(B1[n * 8]);
            mma_tf32(acc[n], a0, a1, a2, a3, b0, b1);
        }
    }

    float* o0 = g_k1 + (size_t)(t0 + mt * 16 + gID) * H_DIM + g * DIN + nh * 64;
    float* o1 = o0 + 8 * H_DIM;
#pragma unroll
    for (int n = 0; n < 8; n++) {
        int col = n * 8 + tID * 2;
        *(float2*)&o0[col] = make_float2(acc[n][0], acc[n][1]);
        *(float2*)&o1[col] = make_float2(acc[n][2], acc[n][3]);
    }
}

// ---------------------------------------------------------------------------
// K2: k and v via d-pair ffma2 with transposed weights. 16 tok/block, 256 thr.
// ---------------------------------------------------------------------------
extern "C" __global__ void __launch_bounds__(256, 2)
kv_kernel(const float* __restrict__ hidden,
          const float* __restrict__ p_attn,
          const float* __restrict__ p_expand) {
    extern __shared__ float sm[];
    float* xs = sm;            // 16*1024
    float* ps = sm + 16384;    // 16*128
    const int tid  = threadIdx.x;
    const int tok0 = blockIdx.x * 16;

    {
        const float4* src = (const float4*)(hidden + (size_t)tok0 * H_DIM);
        float4* dst = (float4*)xs;
#pragma unroll
        for (int i = 0; i < 16; i++) dst[tid + i * 256] = src[tid + i * 256];
    }
#pragma unroll
    for (int i = 0; i < 8; i++) {
        int e = tid + i * 256;
        int t = e >> 7, c = e & 127;
        int s = (tok0 + t) & (S_LEN - 1);
        ps[e] = p_attn[(size_t)(64 + c) * P_DIM + pos_idx(s)];
    }
    __syncthreads();

    // ---- V ----
    {
        const int d0 = (tid & 31) * 2;
        const int g  = (tid >> 5) * 2;
        const u64* wv0 = (const u64*)(g_WvT + g * 1024 + d0);
        const u64* wv1 = (const u64*)(g_WvT + (g + 1) * 1024 + d0);
        const u64 pe0 = pack2b(p_expand[32 + g]);
        const u64 pe1 = pack2b(p_expand[33 + g]);
#pragma unroll
        for (int th = 0; th < 2; th++) {
            u64 acc[2][8];
#pragma unroll
            for (int t = 0; t < 8; t++) { acc[0][t] = 0ull; acc[1][t] = 0ull; }
#pragma unroll
            for (int h = 0; h < NH; h++) {
                u64 w0 = wv0[h * 32], w1 = wv1[h * 32];
#pragma unroll
                for (int t = 0; t < 8; t++) {
                    u64 x = *(const u64*)&xs[(th * 8 + t) * 1024 + h * 64 + d0];
                    acc[0][t] = ffma2(x, w0, acc[0][t]);
                    acc[1][t] = ffma2(x, w1, acc[1][t]);
                }
            }
#pragma unroll
            for (int t = 0; t < 8; t++) {
                int tt = th * 8 + t;
                u64 pv = *(const u64*)&ps[tt * 128 + 64 + d0];
                float* vb = g_v + (size_t)(tok0 + tt) * H_DIM;
                *(u64*)&vb[g * 64 + d0]       = ffma2(pe0, pv, acc[0][t]);
                *(u64*)&vb[(g + 1) * 64 + d0] = ffma2(pe1, pv, acc[1][t]);
            }
        }
    }
    // ---- K ----
    __syncthreads();
    {
        const float4* src = (const float4*)(g_k1 + (size_t)tok0 * H_DIM);
        float4* dst = (float4*)xs;
#pragma unroll
        for (int i = 0; i < 16; i++) dst[tid + i * 256] = src[tid + i * 256];
    }
    __syncthreads();
    {
        const int dd0 = (tid & 63) * 2;
        const int h8  = (tid >> 6) * 2;
        const u64* wk0 = (const u64*)(g_WkhT + h8 * 1024 + dd0);
        const u64* wk1 = (const u64*)(g_WkhT + (h8 + 1) * 1024 + dd0);
        const int jj0 = h8 * 128 + dd0;
        const int jj1 = (h8 + 1) * 128 + dd0;
        const u64 pe0 = pack2b(p_expand[16 + (jj0 >> 6)]);
        const u64 pe1 = pack2b(p_expand[16 + (jj1 >> 6)]);
        const int d64 = dd0 & 63;
#pragma unroll
        for (int th = 0; th < 2; th++) {
            u64 acc[2][8];
#pragma unroll
            for (int t = 0; t < 8; t++) { acc[0][t] = 0ull; acc[1][t] = 0ull; }
#pragma unroll
            for (int g = 0; g < 8; g++) {
                u64 w0 = wk0[g * 64], w1 = wk1[g * 64];
#pragma unroll
                for (int t = 0; t < 8; t++) {
                    u64 x = *(const u64*)&xs[(th * 8 + t) * 1024 + g * 128 + dd0];
                    acc[0][t] = ffma2(x, w0, acc[0][t]);
                    acc[1][t] = ffma2(x, w1, acc[1][t]);
                }
            }
#pragma unroll
            for (int t = 0; t < 8; t++) {
                int tt = th * 8 + t;
                u64 pk = *(const u64*)&ps[tt * 128 + d64];
                float* kb = g_k + (size_t)(tok0 + tt) * H_DIM;
                *(u64*)&kb[jj0] = ffma2(pe0, pk, acc[0][t]);
                *(u64*)&kb[jj1] = ffma2(pe1, pk, acc[1][t]);
            }
        }
    }
}

// ---------------------------------------------------------------------------
// K3: MT[e][d] += sum_t v[t,e]*k[t,d] per 64-token chunk via tf32 mma.
// grid (32,16,2), 128 thr. Raw fp32 bits as tf32 operands (no cvt).
// ---------------------------------------------------------------------------
extern "C" __global__ void mpart_kernel() {
    __shared__ float vs[64 * 72];
    __shared__ float ks[64 * 72];
    const int c = blockIdx.x, h = blockIdx.y, b = blockIdx.z;
    const int tid = threadIdx.x;
    const size_t tokbase = (size_t)(b * S_LEN + c * 64);
    const float* vp = g_v + tokbase * H_DIM + h * 64;
    const float* kp = g_k + tokbase * H_DIM + h * 64;
#pragma unroll
    for (int it = 0; it < 8; it++) {
        int i = tid + it * 128;
        int row = i >> 4, c4 = (i & 15) * 4;
        *(float4*)&vs[row * 72 + c4] = *(const float4*)(vp + (size_t)row * H_DIM + c4);
        *(float4*)&ks[row * 72 + c4] = *(const float4*)(kp + (size_t)row * H_DIM + c4);
    }
    __syncthreads();

    const int wid = tid >> 5, lane = tid & 31;
    const int gID = lane >> 2, tID = lane & 3;
    const int e0 = wid * 16;
    float acc[8][4];
#pragma unroll
    for (int n = 0; n < 8; n++)
#pragma unroll
        for (int j = 0; j < 4; j++) acc[n][j] = 0.f;

#pragma unroll
    for (int ks8 = 0; ks8 < 8; ks8++) {
        const int t0 = ks8 * 8;
        u32 a0 = __float_as_uint(vs[(t0 + tID) * 72 + e0 + gID]);
        u32 a1 = __float_as_uint(vs[(t0 + tID) * 72 + e0 + gID + 8]);
        u32 a2 = __float_as_uint(vs[(t0 + tID + 4) * 72 + e0 + gID]);
        u32 a3 = __float_as_uint(vs[(t0 + tID + 4) * 72 + e0 + gID + 8]);
#pragma unroll
        for (int n = 0; n < 8; n++) {
            u32 b0 = __float_as_uint(ks[(t0 + tID) * 72 + n * 8 + gID]);
            u32 b1 = __float_as_uint(ks[(t0 + tID + 4) * 72 + n * 8 + gID]);
            mma_tf32(acc[n], a0, a1, a2, a3, b0, b1);
        }
    }

    float* outp = g_Mall + (size_t)(b * 16 + h) * 4096;
    float* out0 = g_M0   + (size_t)(b * 16 + h) * 4096;
    const int er0 = e0 + gID, er1 = e0 + gID + 8;
#pragma unroll
    for (int n = 0; n < 8; n++) {
        int d = n * 8 + tID * 2;
        atomicAdd(&outp[er0 * 64 + d],     acc[n][0]);
        atomicAdd(&outp[er0 * 64 + d + 1], acc[n][1]);
        atomicAdd(&outp[er1 * 64 + d],     acc[n][2]);
        atomicAdd(&outp[er1 * 64 + d + 1], acc[n][3]);
        if (c == 0) {
            *(float2*)&out0[er0 * 64 + d] = make_float2(acc[n][0], acc[n][1]);
            *(float2*)&out0[er1 * 64 + d] = make_float2(acc[n][2], acc[n][3]);
        }
    }
}

// ---------------------------------------------------------------------------
// K4: Q proj (d-pair into qp), ctx = q @ M via tf32 mma (4 stages x 4 heads),
// Wc (d-pair), gates, blend. 16 tok/block, 512 thr, 225.4KB smem, 1 CTA/SM.
// smem floats:
//   X    [0, 16384)       hidden -> C (ctx results, [t][h*64+e])
//   qp   [16384, 35840)   q (fp32 bits used as tf32): head*1216 + t*76 + d
//   Mbuf [35840, 55296)   MT stage: hh*4864 + e*76 + d -> outs after
//   psq  [55296, 56320), gs [56320, 56352)
// ---------------------------------------------------------------------------
extern "C" __global__ void __launch_bounds__(512, 1)
ctx_out_kernel(const float* __restrict__ hidden,
               const float* __restrict__ p_attn,
               const float* __restrict__ p_expand,
               const float* __restrict__ Wg,
               const float* __restrict__ Ug,
               const float* __restrict__ Vg,
               const float* __restrict__ bg,
               float* __restrict__ out) {
    extern __shared__ float sm[];
    float* X    = sm;
    float* qp   = sm + 16384;
    float* Mb   = sm + 35840;
    float* Mout = sm + 35840;
    float* psq  = sm + 55296;
    float* gs   = sm + 56320;
    const int tid  = threadIdx.x;
    const int tok0 = blockIdx.x * 16;
    const int b    = tok0 / S_LEN;
    const int s0   = tok0 & (S_LEN - 1);
    const bool prefix = (s0 < NPF);

    {   // stage hidden into X (4096 float4)
        const float4* src = (const float4*)(hidden + (size_t)tok0 * H_DIM);
        float4* dst = (float4*)X;
#pragma unroll
        for (int i = 0; i < 8; i++) dst[tid + i * 512] = src[tid + i * 512];
    }
#pragma unroll
    for (int i = 0; i < 2; i++) {   // psq: 1024 entries
        int e = tid + i * 512;
        int t = e >> 6, d = e & 63;
        int s = (tok0 + t) & (S_LEN - 1);
        psq[e] = p_attn[(size_t)d * P_DIM + pos_idx(s)];
    }
    __syncthreads();

    // ---- Q -> qp (padded stride 76) : thread = (d-pair, head) ----
    {
        const int d0 = (tid & 31) * 2;
        const int g  = tid >> 5;
        const u64* wq = (const u64*)(g_WqT + g * 1024 + d0);
        u64 acc[16];
#pragma unroll
        for (int t = 0; t < 16; t++) acc[t] = 0ull;
#pragma unroll
        for (int h = 0; h < NH; h++) {
            u64 w = wq[h * 32];
#pragma unroll
            for (int t = 0; t < 16; t++)
                acc[t] = ffma2(*(const u64*)&X[t * 1024 + h * 64 + d0], w, acc[t]);
        }
        const u64 pe2 = pack2b(p_expand[g]);
        float* row = qp + g * 1216 + d0;
#pragma unroll
        for (int t = 0; t < 16; t++) {
            u64 pq = *(const u64*)&psq[t * 64 + d0];
            *(u64*)&row[t * 76] = ffma2(pe2, pq, acc[t]);
        }
    }

    // ---- ctx = q @ M via mma : 4 stages x 4 heads ----
    const int wid  = tid >> 5;
    const int lane = tid & 31;
    const int gID  = lane >> 2, tID = lane & 3;
    const int hh   = wid >> 2;          // head within stage
    const int nq   = wid & 3;           // e quarter (2 n-tiles)
    const float* Ma = g_Mall + (size_t)(b * 16) * 4096;
    const float* M0 = g_M0   + (size_t)(b * 16) * 4096;

    for (int stg = 0; stg < 4; stg++) {
        __syncthreads();
        {   // stage 4 heads of MT into Mb (stride 76)
            const u64* msrc = (const u64*)(Ma + (size_t)stg * 16384);
            const u64* zsrc = (const u64*)(M0 + (size_t)stg * 16384);
#pragma unroll
            for (int i = 0; i < 16; i++) {
                int j = tid + i * 512;                 // 8192 u64
                int h2 = j >> 11, e = (j >> 5) & 63, dp = (j & 31) * 2;
                float* dst = Mb + h2 * 4864 + e * 76 + dp;
                if (prefix) {
                    float2 A = unpk(msrc[j]), Z = unpk(zsrc[j]);
                    dst[0] = A.x - Z.x; dst[1] = A.y - Z.y;
                } else {
                    *(u64*)dst = msrc[j];
                }
            }
        }
        __syncthreads();

        const int head = stg * 4 + hh;
        const float* qb = qp + head * 1216;
        const float* mb = Mb + hh * 4864;
        float acc[2][4];
#pragma unroll
        for (int j = 0; j < 2; j++)
#pragma unroll
            for (int i = 0; i < 4; i++) acc[j][i] = 0.f;
#pragma unroll
        for (int ks8 = 0; ks8 < 8; ks8++) {
            const int k0 = ks8 * 8;
            u32 a0 = __float_as_uint(qb[gID * 76 + k0 + tID]);
            u32 a1 = __float_as_uint(qb[(gID + 8) * 76 + k0 + tID]);
            u32 a2 = __float_as_uint(qb[gID * 76 + k0 + tID + 4]);
            u32 a3 = __float_as_uint(qb[(gID + 8) * 76 + k0 + tID + 4]);
#pragma unroll
            for (int j = 0; j < 2; j++) {
                int nt = nq * 2 + j;
                u32 b0 = __float_as_uint(mb[(nt * 8 + gID) * 76 + k0 + tID]);
                u32 b1 = __float_as_uint(mb[(nt * 8 + gID) * 76 + k0 + tID + 4]);
                mma_tf32(acc[j], a0, a1, a2, a3, b0, b1);
            }
        }
#pragma unroll
        for (int j = 0; j < 2; j++) {
            int col = head * 64 + (nq * 2 + j) * 8 + 2 * tID;
            *(float2*)&X[gID * 1024 + col]       = make_float2(acc[j][0], acc[j][1]);
            *(float2*)&X[(gID + 8) * 1024 + col] = make_float2(acc[j][2], acc[j][3]);
        }
    }
    __syncthreads();   // ctx complete in X; Mb free

    // ---- out = Wc head-mix (d-pair): read X(C), write outs into Mout ----
    {
        const int d0 = (tid & 31) * 2;
        const int g  = tid >> 5;
        const u64* wc = (const u64*)(g_WcT + g * 1024 + d0);
        u64 acc[16];
#pragma unroll
        for (int t = 0; t < 16; t++) acc[t] = 0ull;
#pragma unroll
        for (int h = 0; h < NH; h++) {
            u64 w = wc[h * 32];
#pragma unroll
            for (int t = 0; t < 16; t++)
                acc[t] = ffma2(*(const u64*)&X[t * 1024 + h * 64 + d0], w, acc[t]);
        }
        __syncthreads();
#pragma unroll
        for (int t = 0; t < 16; t++)
            *(u64*)&Mout[t * 1024 + g * 64 + d0] = acc[t];
    }
    __syncthreads();

    // ---- gates: one warp per token; hidden re-read from global (L2-hot) ----
    {
        const int t = tid >> 5, sub = tid & 31;
        const float* hrow = hidden + (size_t)(tok0 + t) * H_DIM;
        float a0 = 0.f, a1 = 0.f;
#pragma unroll 8
        for (int k = 0; k < 32; k++) {
            int j = sub + k * 32;
            float hv = hrow[j];
            float ov = Mout[t * 1024 + j];
            a0 += hv * Wg[j]        + ov * Ug[j];
            a1 += hv * Wg[1024 + j] + ov * Ug[1024 + j];
        }
#pragma unroll
        for (int off = 16; off >= 1; off >>= 1) {
            a0 += __shfl_xor_sync(0xffffffffu, a0, off);
            a1 += __shfl_xor_sync(0xffffffffu, a1, off);
        }
        if (sub == 0) {
            int s  = (tok0 + t) & (S_LEN - 1);
            int ip = pos_idx(s);
            float z0 = a0 + Vg[ip] + bg[0];
            float z1 = a1 + Vg[P_DIM + ip] + bg[1];
            gs[t * 2]     = 1.f / (1.f + expf(-z0));
            gs[t * 2 + 1] = 1.f / (1.f + expf(-z1));
        }
    }
    __syncthreads();

    // ---- final blend (hidden from global, outs from Mout) ----
    {
        const float4* hsrc = (const float4*)(hidden + (size_t)tok0 * H_DIM);
        float4* od = (float4*)out;
#pragma unroll
        for (int i = 0; i < 8; i++) {
            int idx = tid + i * 512;
            int t = idx >> 8;
            float g0 = gs[t * 2], g1 = gs[t * 2 + 1];
            float4 ov = ((float4*)Mout)[idx];
            float4 hv = hsrc[idx];
            od[(size_t)tok0 * 256 + idx] =
                make_float4(g0 * ov.x + g1 * hv.x, g0 * ov.y + g1 * hv.y,
                            g0 * ov.z + g1 * hv.z, g0 * ov.w + g1 * hv.w);
        }
    }
}

// ---------------------------------------------------------------------------
extern "C" void kernel_launch(void* const* d_in, const int* in_sizes, int n_in,
                              void* d_out, int out_size) {
    const float* hidden   = (const float*)d_in[0];
    const float* Wq       = (const float*)d_in[3];
    const float* Wkg      = (const float*)d_in[4];
    const float* Wkh      = (const float*)d_in[5];
    const float* Wv       = (const float*)d_in[6];
    const float* p_attn   = (const float*)d_in[7];
    const float* p_expand = (const float*)d_in[8];
    const float* Wc       = (const float*)d_in[9];
    const float* Wg       = (const float*)d_in[10];
    const float* Ug       = (const float*)d_in[11];
    const float* Vg       = (const float*)d_in[12];
    const float* bg       = (const float*)d_in[13];
    float* out = (float*)d_out;

    cudaFuncSetAttribute(wprep_kernel,   cudaFuncAttributeMaxDynamicSharedMemorySize, 65536);
    cudaFuncSetAttribute(k1_kernel,      cudaFuncAttributeMaxDynamicSharedMemorySize, 103424);
    cudaFuncSetAttribute(kv_kernel,      cudaFuncAttributeMaxDynamicSharedMemorySize, 73728);
    cudaFuncSetAttribute(ctx_out_kernel, cudaFuncAttributeMaxDynamicSharedMemorySize, 225408);

    wprep_kernel<<<4, 256, 65536>>>(Wq, Wv, Wc, Wkh);
    k1_kernel<<<dim3(64, 8), 256, 103424>>>(hidden, Wkg);
    kv_kernel<<<256, 256, 73728>>>(hidden, p_attn, p_expand);
    mpart_kernel<<<dim3(32, 16, 2), 128>>>();
    ctx_out_kernel<<<256, 512, 225408>>>(hidden, p_attn, p_expand,
                                         Wg, Ug, Vg, bg, out);
}